// round 9
// baseline (speedup 1.0000x reference)
#include <cuda_runtime.h>

#define NN  100000
#define NE  1600000
#define IN_DIM  64
#define HID_DIM 48
#define OUT_DIM 32

#define SCAN_B 512
#define SCAN_NBLK ((NN + SCAN_B - 1) / SCAN_B)
#define NBKT 128                                  // degree buckets

// ---------------------------------------------------------------------------
// Scratch (device globals)
// ---------------------------------------------------------------------------
__device__ float g_h0  [(size_t)NN * HID_DIM];
__device__ float g_out1[(size_t)NN * HID_DIM];
__device__ float g_h1  [(size_t)NN * OUT_DIM];
__device__ float g_dis [NN];
__device__ int2  g_edge[NE];                     // parsed (src, dst)
__device__ int2  g_erec[NE];                     // CSR records: (src, bitcast norm)
__device__ int   g_cnt [NN];
__device__ int   g_fill[NN];
__device__ int   g_rowptr[NN + 1];
__device__ int   g_part[NN];
__device__ int   g_bsum[SCAN_NBLK];
__device__ int   g_perm[NN];                     // nodes sorted by degree
__device__ int   g_hist[NBKT];
__device__ int   g_hstart[NBKT];
__device__ int   g_hcur[NBKT];
__device__ int   g_is64;

// ---------------------------------------------------------------------------
// Zero counters + warp-parallel dtype detect (block 0, warp 0)
// ---------------------------------------------------------------------------
__global__ void k_zero(const int* __restrict__ raw, int n) {
    int i = blockIdx.x * blockDim.x + threadIdx.x;
    if (i < n) { g_cnt[i] = 0; g_fill[i] = 0; }
    if (i < NBKT) { g_hist[i] = 0; g_hcur[i] = 0; }
    if (blockIdx.x == 0 && threadIdx.x < 32) {
        int w = raw[threadIdx.x * 2 + 1];                 // odd int32 words
        unsigned nz = __ballot_sync(0xFFFFFFFFu, w != 0);
        if (threadIdx.x == 0) g_is64 = (nz == 0u);
    }
}

// Parse raw edges -> int2 AND count in-degrees (fused).
__global__ void k_convert(const void* __restrict__ raw, int e) {
    int i = blockIdx.x * blockDim.x + threadIdx.x;
    if (i >= e) return;
    int s, d;
    if (g_is64) {
        const long long* p = (const long long*)raw;
        s = (int)p[i];
        d = (int)p[e + i];
    } else {
        const int* p = (const int*)raw;
        s = p[i];
        d = p[e + i];
    }
    s = min(max(s, 0), NN - 1);
    d = min(max(d, 0), NN - 1);
    g_edge[i] = make_int2(s, d);
    atomicAdd(&g_cnt[d], 1);
}

// ---------------------------------------------------------------------------
// Pass 1: block scan of g_cnt + dis + block-local degree histogram
// ---------------------------------------------------------------------------
__global__ void k_scan1(int n) {
    __shared__ int sh[SCAN_B];
    __shared__ int lh[NBKT];
    if (threadIdx.x < NBKT) lh[threadIdx.x] = 0;
    __syncthreads();

    int i = blockIdx.x * SCAN_B + threadIdx.x;
    int v = (i < n) ? g_cnt[i] : 0;
    if (i < n) {
        g_dis[i] = rsqrtf((float)(v + 1));                 // +1 self-loop
        atomicAdd(&lh[min(v, NBKT - 1)], 1);
    }
    sh[threadIdx.x] = v;
    __syncthreads();
#pragma unroll
    for (int off = 1; off < SCAN_B; off <<= 1) {
        int t = (threadIdx.x >= off) ? sh[threadIdx.x - off] : 0;
        __syncthreads();
        sh[threadIdx.x] += t;
        __syncthreads();
    }
    if (i < n) g_part[i] = sh[threadIdx.x] - v;            // exclusive
    if (threadIdx.x == SCAN_B - 1) g_bsum[blockIdx.x] = sh[SCAN_B - 1];
    if (threadIdx.x < NBKT && lh[threadIdx.x] > 0)
        atomicAdd(&g_hist[threadIdx.x], lh[threadIdx.x]);
}

// ---------------------------------------------------------------------------
// Pass 2 (one block, 256 thr): shfl scan of block sums AND degree histogram
// ---------------------------------------------------------------------------
__device__ __forceinline__ int block_excl_scan_256(int v, int* ws) {
    __syncthreads();                                       // ws reuse hazard
    int lane = threadIdx.x & 31, w = threadIdx.x >> 5;
    int inc = v;
#pragma unroll
    for (int off = 1; off < 32; off <<= 1) {
        int y = __shfl_up_sync(0xFFFFFFFFu, inc, off);
        if (lane >= off) inc += y;
    }
    if (lane == 31) ws[w] = inc;
    __syncthreads();
    if (threadIdx.x < 8) {
        int t = ws[threadIdx.x];
        int s = t;
#pragma unroll
        for (int off = 1; off < 8; off <<= 1) {
            int y = __shfl_up_sync(0x000000FFu, s, off);
            if (threadIdx.x >= off) s += y;
        }
        ws[threadIdx.x] = s - t;                           // exclusive warp base
    }
    __syncthreads();
    return inc - v + ws[w];
}

__global__ void k_scan2() {
    __shared__ int ws[8];
    int t = threadIdx.x;
    int v = (t < SCAN_NBLK) ? g_bsum[t] : 0;               // SCAN_NBLK <= 256
    int ex = block_excl_scan_256(v, ws);
    if (t < SCAN_NBLK) g_bsum[t] = ex;

    int h = (t < NBKT) ? g_hist[t] : 0;
    int hx = block_excl_scan_256(h, ws);
    if (t < NBKT) g_hstart[t] = hx;
}

// ---------------------------------------------------------------------------
// Pass 3: rowptr finalize + degree-sorted permutation scatter
// ---------------------------------------------------------------------------
__global__ void k_scan3(int n, int e) {
    __shared__ int lbase[NBKT];                            // local hist -> global base
    __shared__ int lcur [NBKT];
    if (threadIdx.x < NBKT) { lbase[threadIdx.x] = 0; lcur[threadIdx.x] = 0; }
    __syncthreads();

    int i = blockIdx.x * SCAN_B + threadIdx.x;
    int dg = -1;
    if (i < n) {
        g_rowptr[i] = g_part[i] + g_bsum[blockIdx.x];
        dg = min(g_cnt[i], NBKT - 1);
        atomicAdd(&lbase[dg], 1);
    }
    if (i == 0) g_rowptr[n] = e;
    __syncthreads();
    if (threadIdx.x < NBKT && lbase[threadIdx.x] > 0)
        lbase[threadIdx.x] = atomicAdd(&g_hcur[threadIdx.x], lbase[threadIdx.x]);
    __syncthreads();
    if (i < n) {
        int loc = atomicAdd(&lcur[dg], 1);
        g_perm[g_hstart[dg] + lbase[dg] + loc] = i;
    }
}

// ---------------------------------------------------------------------------
// CSR fill from parsed edges: record = (src, norm)
// ---------------------------------------------------------------------------
__global__ void k_fill(int e) {
    int i = blockIdx.x * blockDim.x + threadIdx.x;
    if (i >= e) return;
    int2 ed = g_edge[i];
    float nm = g_dis[ed.x] * g_dis[ed.y];
    int pos = g_rowptr[ed.y] + atomicAdd(&g_fill[ed.y], 1);
    g_erec[pos] = make_int2(ed.x, __float_as_int(nm));
}

// ---------------------------------------------------------------------------
// Dense transform: H[n,F] = (relu?)(X[n,K]) @ W[K,F]
// ---------------------------------------------------------------------------
template <int K, int F, bool RELU_IN>
__global__ void k_gemm(const float* __restrict__ X,
                       const float* __restrict__ W,
                       float* __restrict__ H, int n) {
    constexpr int G = F / 4;
    __shared__ float Ws[K * F];
    for (int i = threadIdx.x; i < K * F; i += blockDim.x) Ws[i] = W[i];
    __syncthreads();

    int tid = blockIdx.x * blockDim.x + threadIdx.x;
    int row = tid / G;
    int g   = tid % G;
    if (row >= n) return;

    const float* xr = X + (size_t)row * K;
    float4 acc = make_float4(0.f, 0.f, 0.f, 0.f);
#pragma unroll
    for (int k = 0; k < K; k++) {
        float xv = xr[k];
        if (RELU_IN) xv = fmaxf(xv, 0.f);
        float4 w = *reinterpret_cast<const float4*>(&Ws[k * F + g * 4]);
        acc.x = fmaf(xv, w.x, acc.x);
        acc.y = fmaf(xv, w.y, acc.y);
        acc.z = fmaf(xv, w.z, acc.z);
        acc.w = fmaf(xv, w.w, acc.w);
    }
    *reinterpret_cast<float4*>(&H[(size_t)row * F + g * 4]) = acc;
}

// ---------------------------------------------------------------------------
// CSR gather-aggregate, degree-sorted node order (minimal warp divergence):
//   O[v,f] = b[f] + H[v,f]*dis[v]^2 + sum_{(s,nm) in list(v)} H[s,f]*nm
// ---------------------------------------------------------------------------
template <int F>
__global__ void k_aggcsr(const float* __restrict__ H,
                         const float* __restrict__ b,
                         float* __restrict__ O, int n) {
    constexpr int G = F / 4;
    int tid = blockIdx.x * blockDim.x + threadIdx.x;
    int idx = tid / G;
    int g   = tid % G;
    if (idx >= n) return;
    int node = g_perm[idx];                        // degree-sorted order

    size_t o = (size_t)node * F + g * 4;
    float ds = g_dis[node];
    float d2 = ds * ds;
    float4 h  = *reinterpret_cast<const float4*>(&H[o]);
    float4 bv = *reinterpret_cast<const float4*>(&b[g * 4]);
    float4 acc = make_float4(bv.x + h.x * d2, bv.y + h.y * d2,
                             bv.z + h.z * d2, bv.w + h.w * d2);

    int beg = g_rowptr[node];
    int end = g_rowptr[node + 1];
#pragma unroll 2
    for (int j = beg; j < end; j++) {
        int2 r = g_erec[j];                         // broadcast across G threads
        float nm = __int_as_float(r.y);
        float4 v = *reinterpret_cast<const float4*>(&H[(size_t)r.x * F + g * 4]);
        acc.x = fmaf(v.x, nm, acc.x);
        acc.y = fmaf(v.y, nm, acc.y);
        acc.z = fmaf(v.z, nm, acc.z);
        acc.w = fmaf(v.w, nm, acc.w);
    }
    *reinterpret_cast<float4*>(&O[o]) = acc;
}

// ---------------------------------------------------------------------------
// Launch
// ---------------------------------------------------------------------------
static inline int cdiv(long long a, int b) { return (int)((a + b - 1) / b); }

extern "C" void kernel_launch(void* const* d_in, const int* in_sizes, int n_in,
                              void* d_out, int out_size) {
    const float* x   = (const float*)d_in[0];
    const void*  ei  = d_in[1];
    const float* W1  = (const float*)d_in[2];
    const float* b1  = (const float*)d_in[3];
    const float* W2  = (const float*)d_in[4];
    const float* b2  = (const float*)d_in[5];
    float*       out = (float*)d_out;

    const int n = in_sizes[0] / IN_DIM;   // 100000
    const int e = in_sizes[1] / 2;        // 1600000

    float *h0, *out1, *h1;
    cudaGetSymbolAddress((void**)&h0,   g_h0);
    cudaGetSymbolAddress((void**)&out1, g_out1);
    cudaGetSymbolAddress((void**)&h1,   g_h1);

    const int T = 256;

    // CSR build + degree sort
    k_zero   <<<cdiv(n, T), T>>>((const int*)ei, n);
    k_convert<<<cdiv(e, T), T>>>(ei, e);
    k_scan1  <<<SCAN_NBLK, SCAN_B>>>(n);
    k_scan2  <<<1, 256>>>();
    k_scan3  <<<SCAN_NBLK, SCAN_B>>>(n, e);
    k_fill   <<<cdiv(e, T), T>>>(e);

    // Layer 1
    k_gemm<IN_DIM, HID_DIM, false><<<cdiv((long long)n * (HID_DIM / 4), T), T>>>(x, W1, h0, n);
    k_aggcsr<HID_DIM><<<cdiv((long long)n * (HID_DIM / 4), T), T>>>(h0, b1, out1, n);

    // Layer 2
    k_gemm<HID_DIM, OUT_DIM, true><<<cdiv((long long)n * (OUT_DIM / 4), T), T>>>(out1, W2, h1, n);
    k_aggcsr<OUT_DIM><<<cdiv((long long)n * (OUT_DIM / 4), T), T>>>(h1, b2, out, n);
}

// round 10
// speedup vs baseline: 1.0117x; 1.0117x over previous
#include <cuda_runtime.h>

#define NN  100000
#define NE  1600000
#define IN_DIM  64
#define HID_DIM 48
#define OUT_DIM 32

#define SCAN_B 512
#define SCAN_NBLK ((NN + SCAN_B - 1) / SCAN_B)

// ---------------------------------------------------------------------------
// Scratch (device globals)
// ---------------------------------------------------------------------------
__device__ float g_h0  [(size_t)NN * HID_DIM];
__device__ float g_out1[(size_t)NN * HID_DIM];
__device__ float g_h1  [(size_t)NN * OUT_DIM];
__device__ float g_dis [NN];
__device__ int2  g_edge[NE];                     // parsed (src, dst)
__device__ int2  g_erec[NE];                     // CSR records: (src, bitcast norm)
__device__ int   g_cnt [NN];
__device__ int   g_fill[NN];
__device__ int   g_rowptr[NN + 1];
__device__ int   g_part[NN];
__device__ int   g_bsum[SCAN_NBLK];
__device__ int   g_is64;

// ---------------------------------------------------------------------------
// Zero counters + warp-parallel dtype detect (block 0, warp 0):
// int64 values < 2^31 ==> all odd int32 words zero. 32 parallel probes.
// ---------------------------------------------------------------------------
__global__ void k_zero(const int* __restrict__ raw, int n) {
    int i = blockIdx.x * blockDim.x + threadIdx.x;
    if (i < n) { g_cnt[i] = 0; g_fill[i] = 0; }
    if (blockIdx.x == 0 && threadIdx.x < 32) {
        int w = raw[threadIdx.x * 2 + 1];                 // odd int32 words
        unsigned nz = __ballot_sync(0xFFFFFFFFu, w != 0);
        if (threadIdx.x == 0) g_is64 = (nz == 0u);
    }
}

// Parse raw edges -> int2 AND count in-degrees (fused).
__global__ void k_convert(const void* __restrict__ raw, int e) {
    int i = blockIdx.x * blockDim.x + threadIdx.x;
    if (i >= e) return;
    int s, d;
    if (g_is64) {
        const long long* p = (const long long*)raw;
        s = (int)p[i];
        d = (int)p[e + i];
    } else {
        const int* p = (const int*)raw;
        s = p[i];
        d = p[e + i];
    }
    s = min(max(s, 0), NN - 1);                   // defensive clamp (no trap)
    d = min(max(d, 0), NN - 1);
    g_edge[i] = make_int2(s, d);
    atomicAdd(&g_cnt[d], 1);
}

// ---------------------------------------------------------------------------
// Exclusive scan of g_cnt (3 kernels); dis computed in pass 1 (fused).
// ---------------------------------------------------------------------------
__global__ void k_scan1(int n) {
    __shared__ int sh[SCAN_B];
    int i = blockIdx.x * SCAN_B + threadIdx.x;
    int v = (i < n) ? g_cnt[i] : 0;
    if (i < n) g_dis[i] = rsqrtf((float)(v + 1));          // +1 self-loop
    sh[threadIdx.x] = v;
    __syncthreads();
#pragma unroll
    for (int off = 1; off < SCAN_B; off <<= 1) {
        int t = (threadIdx.x >= off) ? sh[threadIdx.x - off] : 0;
        __syncthreads();
        sh[threadIdx.x] += t;
        __syncthreads();
    }
    if (i < n) g_part[i] = sh[threadIdx.x] - v;            // exclusive
    if (threadIdx.x == SCAN_B - 1) g_bsum[blockIdx.x] = sh[SCAN_B - 1];
}

// One block, 256 threads: shfl-based exclusive scan of block sums.
__global__ void k_scan2() {
    __shared__ int ws[8];
    int t = threadIdx.x;
    int lane = t & 31, w = t >> 5;
    int v = (t < SCAN_NBLK) ? g_bsum[t] : 0;               // SCAN_NBLK <= 256
    int inc = v;
#pragma unroll
    for (int off = 1; off < 32; off <<= 1) {
        int y = __shfl_up_sync(0xFFFFFFFFu, inc, off);
        if (lane >= off) inc += y;
    }
    if (lane == 31) ws[w] = inc;
    __syncthreads();
    if (t < 8) {
        int x = ws[t];
        int s = x;
#pragma unroll
        for (int off = 1; off < 8; off <<= 1) {
            int y = __shfl_up_sync(0x000000FFu, s, off);
            if (t >= off) s += y;
        }
        ws[t] = s - x;                                      // exclusive warp base
    }
    __syncthreads();
    if (t < SCAN_NBLK) g_bsum[t] = inc - v + ws[w];
}

__global__ void k_scan3(int n, int e) {
    int i = blockIdx.x * SCAN_B + threadIdx.x;
    if (i < n) g_rowptr[i] = g_part[i] + g_bsum[blockIdx.x];
    if (i == 0) g_rowptr[n] = e;
}

// ---------------------------------------------------------------------------
// CSR fill from parsed edges: record = (src, norm)
// ---------------------------------------------------------------------------
__global__ void k_fill(int e) {
    int i = blockIdx.x * blockDim.x + threadIdx.x;
    if (i >= e) return;
    int2 ed = g_edge[i];
    float nm = g_dis[ed.x] * g_dis[ed.y];
    int pos = g_rowptr[ed.y] + atomicAdd(&g_fill[ed.y], 1);
    g_erec[pos] = make_int2(ed.x, __float_as_int(nm));
}

// ---------------------------------------------------------------------------
// Dense transform: H[n,F] = (relu?)(X[n,K]) @ W[K,F]
// ---------------------------------------------------------------------------
template <int K, int F, bool RELU_IN>
__global__ void k_gemm(const float* __restrict__ X,
                       const float* __restrict__ W,
                       float* __restrict__ H, int n) {
    constexpr int G = F / 4;
    __shared__ float Ws[K * F];
    for (int i = threadIdx.x; i < K * F; i += blockDim.x) Ws[i] = W[i];
    __syncthreads();

    int tid = blockIdx.x * blockDim.x + threadIdx.x;
    int row = tid / G;
    int g   = tid % G;
    if (row >= n) return;

    const float* xr = X + (size_t)row * K;
    float4 acc = make_float4(0.f, 0.f, 0.f, 0.f);
#pragma unroll
    for (int k = 0; k < K; k++) {
        float xv = xr[k];
        if (RELU_IN) xv = fmaxf(xv, 0.f);
        float4 w = *reinterpret_cast<const float4*>(&Ws[k * F + g * 4]);
        acc.x = fmaf(xv, w.x, acc.x);
        acc.y = fmaf(xv, w.y, acc.y);
        acc.z = fmaf(xv, w.z, acc.z);
        acc.w = fmaf(xv, w.w, acc.w);
    }
    *reinterpret_cast<float4*>(&H[(size_t)row * F + g * 4]) = acc;
}

// ---------------------------------------------------------------------------
// CSR gather-aggregate (no atomics) — proven R8 form:
//   O[v,f] = b[f] + H[v,f]*dis[v]^2 + sum_{(s,nm) in list(v)} H[s,f]*nm
// ---------------------------------------------------------------------------
template <int F>
__global__ void k_aggcsr(const float* __restrict__ H,
                         const float* __restrict__ b,
                         float* __restrict__ O, int n) {
    constexpr int G = F / 4;
    int tid = blockIdx.x * blockDim.x + threadIdx.x;
    int node = tid / G;
    int g    = tid % G;
    if (node >= n) return;

    size_t o = (size_t)node * F + g * 4;
    float ds = g_dis[node];
    float d2 = ds * ds;
    float4 h  = *reinterpret_cast<const float4*>(&H[o]);
    float4 bv = *reinterpret_cast<const float4*>(&b[g * 4]);
    float4 acc = make_float4(bv.x + h.x * d2, bv.y + h.y * d2,
                             bv.z + h.z * d2, bv.w + h.w * d2);

    int beg = g_rowptr[node];
    int end = g_rowptr[node + 1];
#pragma unroll 2
    for (int j = beg; j < end; j++) {
        int2 r = g_erec[j];                         // broadcast across G threads
        float nm = __int_as_float(r.y);
        float4 v = *reinterpret_cast<const float4*>(&H[(size_t)r.x * F + g * 4]);
        acc.x = fmaf(v.x, nm, acc.x);
        acc.y = fmaf(v.y, nm, acc.y);
        acc.z = fmaf(v.z, nm, acc.z);
        acc.w = fmaf(v.w, nm, acc.w);
    }
    *reinterpret_cast<float4*>(&O[o]) = acc;
}

// ---------------------------------------------------------------------------
// Launch: fork gemm1 onto a side stream, concurrent with the CSR build.
// Stream/events are created once on the first (uncaptured correctness) call;
// the captured graph contains only launches + fork/join edges.
// ---------------------------------------------------------------------------
static inline int cdiv(long long a, int b) { return (int)((a + b - 1) / b); }

extern "C" void kernel_launch(void* const* d_in, const int* in_sizes, int n_in,
                              void* d_out, int out_size) {
    const float* x   = (const float*)d_in[0];
    const void*  ei  = d_in[1];
    const float* W1  = (const float*)d_in[2];
    const float* b1  = (const float*)d_in[3];
    const float* W2  = (const float*)d_in[4];
    const float* b2  = (const float*)d_in[5];
    float*       out = (float*)d_out;

    const int n = in_sizes[0] / IN_DIM;   // 100000
    const int e = in_sizes[1] / 2;        // 1600000

    float *h0, *out1, *h1;
    cudaGetSymbolAddress((void**)&h0,   g_h0);
    cudaGetSymbolAddress((void**)&out1, g_out1);
    cudaGetSymbolAddress((void**)&h1,   g_h1);

    static cudaStream_t s2 = nullptr;
    static cudaEvent_t  evF = nullptr, evJ = nullptr;
    if (!s2) {
        cudaStreamCreateWithFlags(&s2, cudaStreamNonBlocking);
        cudaEventCreateWithFlags(&evF, cudaEventDisableTiming);
        cudaEventCreateWithFlags(&evJ, cudaEventDisableTiming);
    }

    const int T = 256;

    // Fork: gemm1 is independent of the CSR build.
    cudaEventRecord(evF, 0);
    cudaStreamWaitEvent(s2, evF, 0);
    k_gemm<IN_DIM, HID_DIM, false><<<cdiv((long long)n * (HID_DIM / 4), T), T, 0, s2>>>(x, W1, h0, n);
    cudaEventRecord(evJ, s2);

    // CSR build on the main stream (concurrent with gemm1).
    k_zero   <<<cdiv(n, T), T>>>((const int*)ei, n);
    k_convert<<<cdiv(e, T), T>>>(ei, e);
    k_scan1  <<<SCAN_NBLK, SCAN_B>>>(n);
    k_scan2  <<<1, 256>>>();
    k_scan3  <<<SCAN_NBLK, SCAN_B>>>(n, e);
    k_fill   <<<cdiv(e, T), T>>>(e);

    // Join: agg1 needs both h0 (gemm1) and the CSR.
    cudaStreamWaitEvent(0, evJ, 0);
    k_aggcsr<HID_DIM><<<cdiv((long long)n * (HID_DIM / 4), T), T>>>(h0, b1, out1, n);

    // Layer 2 (dependent chain).
    k_gemm<HID_DIM, OUT_DIM, true><<<cdiv((long long)n * (OUT_DIM / 4), T), T>>>(out1, W2, h1, n);
    k_aggcsr<OUT_DIM><<<cdiv((long long)n * (OUT_DIM / 4), T), T>>>(h1, b2, out, n);
}

// round 11
// speedup vs baseline: 1.1257x; 1.1126x over previous
#include <cuda_runtime.h>

#define NN  100000
#define NE  1600000
#define IN_DIM  64
#define HID_DIM 48
#define OUT_DIM 32

#define SCAN_B 512
#define SCAN_NBLK ((NN + SCAN_B - 1) / SCAN_B)

// ---------------------------------------------------------------------------
// Scratch (device globals)
// ---------------------------------------------------------------------------
__device__ float g_h0  [(size_t)NN * HID_DIM];   // (x @ W1) * dis[row]   (pre-scaled)
__device__ float g_out1[(size_t)NN * HID_DIM];   // layer-1 output
__device__ float g_h1  [(size_t)NN * OUT_DIM];   // (relu(out1) @ W2) * dis[row]
__device__ float g_dis [NN];
__device__ int2  g_edge[NE];                     // parsed (src, dst)
__device__ int   g_esrc[NE];                     // CSR records: src only (norm factored out)
__device__ int   g_cnt [NN];
__device__ int   g_fill[NN];
__device__ int   g_rowptr[NN + 1];
__device__ int   g_part[NN];
__device__ int   g_bsum[SCAN_NBLK];
__device__ int   g_is64;

// ---------------------------------------------------------------------------
// Zero counters + warp-parallel dtype detect (block 0, warp 0):
// int64 values < 2^31 ==> all odd int32 words zero. 32 parallel probes.
// ---------------------------------------------------------------------------
__global__ void k_zero(const int* __restrict__ raw, int n) {
    int i = blockIdx.x * blockDim.x + threadIdx.x;
    if (i < n) { g_cnt[i] = 0; g_fill[i] = 0; }
    if (blockIdx.x == 0 && threadIdx.x < 32) {
        int w = raw[threadIdx.x * 2 + 1];                 // odd int32 words
        unsigned nz = __ballot_sync(0xFFFFFFFFu, w != 0);
        if (threadIdx.x == 0) g_is64 = (nz == 0u);
    }
}

// Parse raw edges -> int2 AND count in-degrees. 2 edges per thread (16B loads).
__global__ void k_convert(const void* __restrict__ raw, int e) {
    int i = (blockIdx.x * blockDim.x + threadIdx.x) * 2;
    if (i >= e) return;
    int s0, d0, s1, d1;
    if (g_is64) {
        const longlong2* ps = (const longlong2*)raw;              // src pairs
        const longlong2* pd = (const longlong2*)((const long long*)raw + e);
        longlong2 sv = ps[i >> 1];
        longlong2 dv = pd[i >> 1];
        s0 = (int)sv.x; s1 = (int)sv.y;
        d0 = (int)dv.x; d1 = (int)dv.y;
    } else {
        const int2* ps = (const int2*)raw;
        const int2* pd = (const int2*)((const int*)raw + e);
        int2 sv = ps[i >> 1];
        int2 dv = pd[i >> 1];
        s0 = sv.x; s1 = sv.y;
        d0 = dv.x; d1 = dv.y;
    }
    s0 = min(max(s0, 0), NN - 1); d0 = min(max(d0, 0), NN - 1);
    g_edge[i] = make_int2(s0, d0);
    atomicAdd(&g_cnt[d0], 1);
    if (i + 1 < e) {
        s1 = min(max(s1, 0), NN - 1); d1 = min(max(d1, 0), NN - 1);
        g_edge[i + 1] = make_int2(s1, d1);
        atomicAdd(&g_cnt[d1], 1);
    }
}

// ---------------------------------------------------------------------------
// Exclusive scan of g_cnt (3 kernels); dis computed in pass 1 (fused).
// ---------------------------------------------------------------------------
__global__ void k_scan1(int n) {
    __shared__ int sh[SCAN_B];
    int i = blockIdx.x * SCAN_B + threadIdx.x;
    int v = (i < n) ? g_cnt[i] : 0;
    if (i < n) g_dis[i] = rsqrtf((float)(v + 1));          // +1 self-loop
    sh[threadIdx.x] = v;
    __syncthreads();
#pragma unroll
    for (int off = 1; off < SCAN_B; off <<= 1) {
        int t = (threadIdx.x >= off) ? sh[threadIdx.x - off] : 0;
        __syncthreads();
        sh[threadIdx.x] += t;
        __syncthreads();
    }
    if (i < n) g_part[i] = sh[threadIdx.x] - v;            // exclusive
    if (threadIdx.x == SCAN_B - 1) g_bsum[blockIdx.x] = sh[SCAN_B - 1];
}

// One block, 256 threads: shfl-based exclusive scan of block sums.
__global__ void k_scan2() {
    __shared__ int ws[8];
    int t = threadIdx.x;
    int lane = t & 31, w = t >> 5;
    int v = (t < SCAN_NBLK) ? g_bsum[t] : 0;               // SCAN_NBLK <= 256
    int inc = v;
#pragma unroll
    for (int off = 1; off < 32; off <<= 1) {
        int y = __shfl_up_sync(0xFFFFFFFFu, inc, off);
        if (lane >= off) inc += y;
    }
    if (lane == 31) ws[w] = inc;
    __syncthreads();
    if (t < 8) {
        int x = ws[t];
        int s = x;
#pragma unroll
        for (int off = 1; off < 8; off <<= 1) {
            int y = __shfl_up_sync(0x000000FFu, s, off);
            if (t >= off) s += y;
        }
        ws[t] = s - x;                                      // exclusive warp base
    }
    __syncthreads();
    if (t < SCAN_NBLK) g_bsum[t] = inc - v + ws[w];
}

__global__ void k_scan3(int n, int e) {
    int i = blockIdx.x * SCAN_B + threadIdx.x;
    if (i < n) g_rowptr[i] = g_part[i] + g_bsum[blockIdx.x];
    if (i == 0) g_rowptr[n] = e;
}

// ---------------------------------------------------------------------------
// CSR fill: record = src only (normalization factored into H pre/post scale)
// ---------------------------------------------------------------------------
__global__ void k_fill(int e) {
    int i = blockIdx.x * blockDim.x + threadIdx.x;
    if (i >= e) return;
    int2 ed = g_edge[i];
    int pos = g_rowptr[ed.y] + atomicAdd(&g_fill[ed.y], 1);
    g_esrc[pos] = ed.x;
}

// ---------------------------------------------------------------------------
// Dense transform with pre-scale epilogue:
//   H[r,f] = ((relu?)(X[r,:]) @ W[:,f]) * dis[r]
// ---------------------------------------------------------------------------
template <int K, int F, bool RELU_IN>
__global__ void k_gemm(const float* __restrict__ X,
                       const float* __restrict__ W,
                       float* __restrict__ H, int n) {
    constexpr int G = F / 4;
    __shared__ float Ws[K * F];
    for (int i = threadIdx.x; i < K * F; i += blockDim.x) Ws[i] = W[i];
    __syncthreads();

    int tid = blockIdx.x * blockDim.x + threadIdx.x;
    int row = tid / G;
    int g   = tid % G;
    if (row >= n) return;

    const float* xr = X + (size_t)row * K;
    float4 acc = make_float4(0.f, 0.f, 0.f, 0.f);
#pragma unroll
    for (int k = 0; k < K; k++) {
        float xv = xr[k];
        if (RELU_IN) xv = fmaxf(xv, 0.f);
        float4 w = *reinterpret_cast<const float4*>(&Ws[k * F + g * 4]);
        acc.x = fmaf(xv, w.x, acc.x);
        acc.y = fmaf(xv, w.y, acc.y);
        acc.z = fmaf(xv, w.z, acc.z);
        acc.w = fmaf(xv, w.w, acc.w);
    }
    float ds = g_dis[row];
    acc.x *= ds; acc.y *= ds; acc.z *= ds; acc.w *= ds;
    *reinterpret_cast<float4*>(&H[(size_t)row * F + g * 4]) = acc;
}

// ---------------------------------------------------------------------------
// CSR gather-aggregate with factored normalization:
//   O[v,f] = b[f] + dis[v] * ( Hs[v,f] + sum_{s in list(v)} Hs[s,f] )
// where Hs is the pre-scaled transform output.
// ---------------------------------------------------------------------------
template <int F>
__global__ void k_aggcsr(const float* __restrict__ H,
                         const float* __restrict__ b,
                         float* __restrict__ O, int n) {
    constexpr int G = F / 4;
    int tid = blockIdx.x * blockDim.x + threadIdx.x;
    int node = tid / G;
    int g    = tid % G;
    if (node >= n) return;

    size_t o = (size_t)node * F + g * 4;
    float4 acc = *reinterpret_cast<const float4*>(&H[o]);   // self term (pre-scaled)

    int beg = g_rowptr[node];
    int end = g_rowptr[node + 1];
#pragma unroll 2
    for (int j = beg; j < end; j++) {
        int s = g_esrc[j];                          // broadcast across G threads
        float4 v = *reinterpret_cast<const float4*>(&H[(size_t)s * F + g * 4]);
        acc.x += v.x; acc.y += v.y; acc.z += v.z; acc.w += v.w;
    }
    float ds = g_dis[node];
    float4 bv = *reinterpret_cast<const float4*>(&b[g * 4]);
    float4 ov = make_float4(bv.x + acc.x * ds, bv.y + acc.y * ds,
                            bv.z + acc.z * ds, bv.w + acc.w * ds);
    *reinterpret_cast<float4*>(&O[o]) = ov;
}

// ---------------------------------------------------------------------------
// Launch (single stream — fork experiment regressed)
// ---------------------------------------------------------------------------
static inline int cdiv(long long a, int b) { return (int)((a + b - 1) / b); }

extern "C" void kernel_launch(void* const* d_in, const int* in_sizes, int n_in,
                              void* d_out, int out_size) {
    const float* x   = (const float*)d_in[0];
    const void*  ei  = d_in[1];
    const float* W1  = (const float*)d_in[2];
    const float* b1  = (const float*)d_in[3];
    const float* W2  = (const float*)d_in[4];
    const float* b2  = (const float*)d_in[5];
    float*       out = (float*)d_out;

    const int n = in_sizes[0] / IN_DIM;   // 100000
    const int e = in_sizes[1] / 2;        // 1600000

    float *h0, *out1, *h1;
    cudaGetSymbolAddress((void**)&h0,   g_h0);
    cudaGetSymbolAddress((void**)&out1, g_out1);
    cudaGetSymbolAddress((void**)&h1,   g_h1);

    const int T = 256;

    // CSR build (dis ready after scan1)
    k_zero   <<<cdiv(n, T), T>>>((const int*)ei, n);
    k_convert<<<cdiv(cdiv(e, 2), T), T>>>(ei, e);
    k_scan1  <<<SCAN_NBLK, SCAN_B>>>(n);
    k_scan2  <<<1, 256>>>();
    k_scan3  <<<SCAN_NBLK, SCAN_B>>>(n, e);
    k_fill   <<<cdiv(e, T), T>>>(e);

    // Layer 1 (gemm needs g_dis -> after scan1; chain is serialized anyway)
    k_gemm<IN_DIM, HID_DIM, false><<<cdiv((long long)n * (HID_DIM / 4), T), T>>>(x, W1, h0, n);
    k_aggcsr<HID_DIM><<<cdiv((long long)n * (HID_DIM / 4), T), T>>>(h0, b1, out1, n);

    // Layer 2
    k_gemm<HID_DIM, OUT_DIM, true><<<cdiv((long long)n * (OUT_DIM / 4), T), T>>>(out1, W2, h1, n);
    k_aggcsr<OUT_DIM><<<cdiv((long long)n * (OUT_DIM / 4), T), T>>>(h1, b2, out, n);
}